// round 1
// baseline (speedup 1.0000x reference)
#include <cuda_runtime.h>
#include <math.h>

#define G_DIM   2304
#define HIDDEN  150
#define N_PAIRS 32768
#define N_MENT  4096
#define N_SEG   1024

#define BM 64
#define BN 160
#define BK 16

// Scratch (static device globals; no allocation in kernel_launch)
__device__ float d_Abuf[N_MENT * 152];   // g_i @ W1[0:2304]      (stride 152)
__device__ float d_Bbuf[N_MENT * 152];   // g_i @ W1[2304:4608]   (stride 152)
__device__ float d_bias[3 * BN];         // phi@W1d + b1 per speaker label
__device__ float d_scores[N_PAIRS];      // pre-softmax coref scores

// ---------------------------------------------------------------------------
// Tiny: bias[s][h] = b1[h] + sum_t speaker_embed[s][t] * W1[(3*G_DIM + t)][h]
// ---------------------------------------------------------------------------
__global__ void bias_kernel(const float* __restrict__ spk,
                            const float* __restrict__ W1,
                            const float* __restrict__ b1) {
    const float* Wd = W1 + (size_t)(3 * G_DIM) * HIDDEN;
    for (int idx = threadIdx.x; idx < 3 * BN; idx += blockDim.x) {
        int s = idx / BN, h = idx % BN;
        float v = 0.f;
        if (h < HIDDEN) {
            v = b1[h];
            #pragma unroll
            for (int t = 0; t < 20; t++)
                v = fmaf(spk[s * 20 + t], Wd[(size_t)t * HIDDEN + h], v);
        }
        d_bias[s * BN + h] = v;
    }
}

// ---------------------------------------------------------------------------
// Precompute GEMM: out[m, h] = sum_k g_i[m,k] * W1[wrow_off + k, h]
// grid = (M/BM, 2): y=0 -> Abuf (off 0), y=1 -> Bbuf (off G_DIM)
// ---------------------------------------------------------------------------
__global__ __launch_bounds__(256)
void gemm_precompute(const float* __restrict__ G,
                     const float* __restrict__ W1) {
    __shared__ float Gs[BK][BM + 1];
    __shared__ float Ws[BK][BN];

    const int tid = threadIdx.x;
    const int tx = tid & 15, ty = tid >> 4;
    const int mBase = blockIdx.x * BM;
    const float* W = W1 + (size_t)(blockIdx.y * G_DIM) * HIDDEN;
    float* out = (blockIdx.y == 0) ? d_Abuf : d_Bbuf;

    float acc[4][10];
    #pragma unroll
    for (int i = 0; i < 4; i++)
        #pragma unroll
        for (int j = 0; j < 10; j++) acc[i][j] = 0.f;

    const int lm = tid >> 2, lq = tid & 3;

    for (int k0 = 0; k0 < G_DIM; k0 += BK) {
        // A tile: rows m, cols k0..k0+16, stored transposed
        float4 v = *reinterpret_cast<const float4*>(
            G + (size_t)(mBase + lm) * G_DIM + k0 + lq * 4);
        Gs[lq * 4 + 0][lm] = v.x; Gs[lq * 4 + 1][lm] = v.y;
        Gs[lq * 4 + 2][lm] = v.z; Gs[lq * 4 + 3][lm] = v.w;

        // W tile (zero-pad h >= HIDDEN)
        #pragma unroll
        for (int it = 0; it < (BK * BN) / 256; it++) {
            int idx = tid + it * 256;
            int r = idx / BN, h = idx % BN;
            Ws[r][h] = (h < HIDDEN) ? W[(size_t)(k0 + r) * HIDDEN + h] : 0.f;
        }
        __syncthreads();

        #pragma unroll
        for (int kk = 0; kk < BK; kk++) {
            float g[4];
            #pragma unroll
            for (int i = 0; i < 4; i++) g[i] = Gs[kk][ty * 4 + i];
            #pragma unroll
            for (int j = 0; j < 10; j++) {
                float w = Ws[kk][tx + 16 * j];
                #pragma unroll
                for (int i = 0; i < 4; i++)
                    acc[i][j] = fmaf(g[i], w, acc[i][j]);
            }
        }
        __syncthreads();
    }

    #pragma unroll
    for (int i = 0; i < 4; i++) {
        int m = mBase + ty * 4 + i;
        #pragma unroll
        for (int j = 0; j < 10; j++) {
            int h = tx + 16 * j;
            if (h < HIDDEN) out[(size_t)m * 152 + h] = acc[i][j];
        }
    }
}

// ---------------------------------------------------------------------------
// Pair kernel: fused bilinear GEMM + MLP epilogue
//   C_p[h] = sum_k g_i[i_p,k]*g_i[j_p,k]*W1c[k,h]
//   h_vec  = relu(C_p + A[i] + B[j] + bias[spk])
//   scores = h_vec @ W2 + b2 + s_i + s_j
// ---------------------------------------------------------------------------
__global__ __launch_bounds__(256)
void pair_kernel(const float* __restrict__ G,
                 const float* __restrict__ W1,
                 const int*   __restrict__ m_ids,
                 const int*   __restrict__ a_ids,
                 const int*   __restrict__ spk_lbl,
                 const float* __restrict__ mscores,
                 const float* __restrict__ W2,
                 const float* __restrict__ b2) {
    __shared__ float Ps[BK][BM + 1];
    __shared__ float Ws[BK][BN];

    const int tid = threadIdx.x;
    const int tx = tid & 15, ty = tid >> 4;
    const int pBase = blockIdx.x * BM;
    const float* W = W1 + (size_t)(2 * G_DIM) * HIDDEN;  // W1c rows

    // Loader role: thread -> (pair lp, quad lq)
    const int lp = tid >> 2, lq = tid & 3;
    const int li = m_ids[pBase + lp];
    const int lj = a_ids[pBase + lp];
    const float* rowI = G + (size_t)li * G_DIM;
    const float* rowJ = G + (size_t)lj * G_DIM;

    float acc[4][10];
    #pragma unroll
    for (int i = 0; i < 4; i++)
        #pragma unroll
        for (int j = 0; j < 10; j++) acc[i][j] = 0.f;

    for (int k0 = 0; k0 < G_DIM; k0 += BK) {
        float4 vi = *reinterpret_cast<const float4*>(rowI + k0 + lq * 4);
        float4 vj = *reinterpret_cast<const float4*>(rowJ + k0 + lq * 4);
        Ps[lq * 4 + 0][lp] = vi.x * vj.x;
        Ps[lq * 4 + 1][lp] = vi.y * vj.y;
        Ps[lq * 4 + 2][lp] = vi.z * vj.z;
        Ps[lq * 4 + 3][lp] = vi.w * vj.w;

        #pragma unroll
        for (int it = 0; it < (BK * BN) / 256; it++) {
            int idx = tid + it * 256;
            int r = idx / BN, h = idx % BN;
            Ws[r][h] = (h < HIDDEN) ? W[(size_t)(k0 + r) * HIDDEN + h] : 0.f;
        }
        __syncthreads();

        #pragma unroll
        for (int kk = 0; kk < BK; kk++) {
            float g[4];
            #pragma unroll
            for (int i = 0; i < 4; i++) g[i] = Ps[kk][ty * 4 + i];
            #pragma unroll
            for (int j = 0; j < 10; j++) {
                float w = Ws[kk][tx + 16 * j];
                #pragma unroll
                for (int i = 0; i < 4; i++)
                    acc[i][j] = fmaf(g[i], w, acc[i][j]);
            }
        }
        __syncthreads();
    }

    // Epilogue
    float w2v[10];
    #pragma unroll
    for (int j = 0; j < 10; j++) {
        int h = tx + 16 * j;
        w2v[j] = (h < HIDDEN) ? W2[h] : 0.f;
    }
    const float bias2 = b2[0];

    #pragma unroll
    for (int i = 0; i < 4; i++) {
        int p = pBase + ty * 4 + i;
        int ii = m_ids[p], jj = a_ids[p], sp = spk_lbl[p];
        float part = 0.f;
        #pragma unroll
        for (int j = 0; j < 10; j++) {
            int h = tx + 16 * j;
            if (h < HIDDEN) {
                float val = acc[i][j]
                          + d_Abuf[(size_t)ii * 152 + h]
                          + d_Bbuf[(size_t)jj * 152 + h]
                          + d_bias[sp * BN + h];
                val = fmaxf(val, 0.f);
                part = fmaf(val, w2v[j], part);
            }
        }
        // reduce across the 16 tx lanes (same half-warp)
        #pragma unroll
        for (int off = 8; off; off >>= 1)
            part += __shfl_xor_sync(0xffffffffu, part, off);
        if (tx == 0)
            d_scores[p] = part + bias2 + mscores[ii] + mscores[jj];
    }
}

// ---------------------------------------------------------------------------
// Ragged softmax with epsilon logit 0. One block per segment (sorted ids).
// out[0:P) = pair probs, out[P:P+S) = epsilon probs.
// ---------------------------------------------------------------------------
__global__ void softmax_kernel(const int* __restrict__ seg_ids,
                               float* __restrict__ out) {
    const int s = blockIdx.x;
    __shared__ int sh_lo, sh_hi;
    __shared__ float red[128];

    if (threadIdx.x == 0) {
        int lo = 0, hi = N_PAIRS;
        while (lo < hi) { int mid = (lo + hi) >> 1; if (seg_ids[mid] < s) lo = mid + 1; else hi = mid; }
        sh_lo = lo;
        hi = N_PAIRS;
        while (lo < hi) { int mid = (lo + hi) >> 1; if (seg_ids[mid] < s + 1) lo = mid + 1; else hi = mid; }
        sh_hi = lo;
    }
    __syncthreads();
    const int lo = sh_lo, hi = sh_hi;

    // max (epsilon logit 0 included via init)
    float m = 0.f;
    for (int p = lo + threadIdx.x; p < hi; p += blockDim.x)
        m = fmaxf(m, d_scores[p]);
    red[threadIdx.x] = m;
    __syncthreads();
    for (int st = 64; st; st >>= 1) {
        if (threadIdx.x < st) red[threadIdx.x] = fmaxf(red[threadIdx.x], red[threadIdx.x + st]);
        __syncthreads();
    }
    m = red[0];
    __syncthreads();

    // sum of exp
    float sum = 0.f;
    for (int p = lo + threadIdx.x; p < hi; p += blockDim.x)
        sum += expf(d_scores[p] - m);
    red[threadIdx.x] = sum;
    __syncthreads();
    for (int st = 64; st; st >>= 1) {
        if (threadIdx.x < st) red[threadIdx.x] += red[threadIdx.x + st];
        __syncthreads();
    }
    const float eps_e = expf(-m);
    const float inv_denom = 1.f / (red[0] + eps_e);

    for (int p = lo + threadIdx.x; p < hi; p += blockDim.x)
        out[p] = expf(d_scores[p] - m) * inv_denom;
    if (threadIdx.x == 0)
        out[N_PAIRS + s] = eps_e * inv_denom;
}

// ---------------------------------------------------------------------------
extern "C" void kernel_launch(void* const* d_in, const int* in_sizes, int n_in,
                              void* d_out, int out_size) {
    const float* g_i            = (const float*)d_in[0];
    const float* mention_scores = (const float*)d_in[1];
    const float* speaker_embed  = (const float*)d_in[2];
    const float* W1             = (const float*)d_in[3];
    const float* b1             = (const float*)d_in[4];
    const float* W2             = (const float*)d_in[5];
    const float* b2             = (const float*)d_in[6];
    const int*   mention_ids    = (const int*)d_in[7];
    const int*   antecedent_ids = (const int*)d_in[8];
    const int*   speaker_labels = (const int*)d_in[9];
    const int*   segment_ids    = (const int*)d_in[10];
    float* out = (float*)d_out;

    bias_kernel<<<1, 256>>>(speaker_embed, W1, b1);
    gemm_precompute<<<dim3(N_MENT / BM, 2), 256>>>(g_i, W1);
    pair_kernel<<<N_PAIRS / BM, 256>>>(g_i, W1, mention_ids, antecedent_ids,
                                       speaker_labels, mention_scores, W2, b2);
    softmax_kernel<<<N_SEG, 128>>>(segment_ids, out);
}

// round 3
// speedup vs baseline: 3.3974x; 3.3974x over previous
#include <cuda_runtime.h>
#include <cstdint>
#include <math.h>

#define G_DIM   2304
#define HIDDEN  150
#define N_PAIRS 32768
#define N_MENT  4096
#define N_SEG   1024

#define TM 128
#define TN 160
#define TK 32
#define NCHUNK (G_DIM / TK)   // 72

#define APAD 36    // A smem row stride (words)
#define BPAD 168   // B smem row stride (words)

// ---------------- device scratch (static; no allocation) -------------------
__device__ float d_Wp[3 * G_DIM * TN];    // W1 sections tf32-rounded, [sec][k][160]
__device__ float d_Abuf[N_MENT * TN];     // g_i @ W1a  (stride 160, cols>=150 zero)
__device__ float d_Bbuf[N_MENT * TN];     // g_i @ W1b
__device__ float d_bias[3 * TN];          // phi@W1d + b1, padded 0
__device__ float d_scores[N_PAIRS];

__device__ __forceinline__ uint32_t f2tf32(float x) {
    uint32_t u;
    asm("cvt.rna.tf32.f32 %0, %1;" : "=r"(u) : "f"(x));
    return u;
}

__device__ __forceinline__ void mma_tf32(float* d, const uint32_t* a,
                                         const uint32_t* b) {
    asm volatile(
        "mma.sync.aligned.m16n8k8.row.col.f32.tf32.tf32.f32 "
        "{%0,%1,%2,%3}, {%4,%5,%6,%7}, {%8,%9}, {%0,%1,%2,%3};"
        : "+f"(d[0]), "+f"(d[1]), "+f"(d[2]), "+f"(d[3])
        : "r"(a[0]), "r"(a[1]), "r"(a[2]), "r"(a[3]), "r"(b[0]), "r"(b[1]));
}

// ---------------------------------------------------------------------------
// Prep: W1 sections -> tf32-rounded, zero-padded to 160 cols. [sec][k][160]
// ---------------------------------------------------------------------------
__global__ void prep_w_kernel(const float* __restrict__ W1) {
    int idx = blockIdx.x * 256 + threadIdx.x;
    if (idx >= 3 * G_DIM * TN) return;
    int sec = idx / (G_DIM * TN);
    int r = idx - sec * (G_DIM * TN);
    int k = r / TN, h = r - k * TN;
    float v = 0.f;
    if (h < HIDDEN)
        v = __uint_as_float(f2tf32(W1[(size_t)(sec * G_DIM + k) * HIDDEN + h]));
    d_Wp[idx] = v;
}

// ---------------------------------------------------------------------------
// bias[s][h] = b1[h] + phi[s] @ W1d[:,h]; padded 0 to TN.
// ---------------------------------------------------------------------------
__global__ void bias_kernel(const float* __restrict__ spk,
                            const float* __restrict__ W1,
                            const float* __restrict__ b1) {
    const float* Wd = W1 + (size_t)(3 * G_DIM) * HIDDEN;
    for (int idx = threadIdx.x; idx < 3 * TN; idx += blockDim.x) {
        int s = idx / TN, h = idx % TN;
        float v = 0.f;
        if (h < HIDDEN) {
            v = b1[h];
            #pragma unroll
            for (int t = 0; t < 20; t++)
                v = fmaf(spk[s * 20 + t], Wd[(size_t)t * HIDDEN + h], v);
        }
        d_bias[idx] = v;
    }
}

// ---------------------------------------------------------------------------
// Unified tf32 mma.sync GEMM kernel.
//   pair_mode==0: out[sec=blockIdx.y] = g_i @ W1[sec] -> d_Abuf / d_Bbuf
//   pair_mode==1: (i∘j)@W1c + fused MLP epilogue -> d_scores
// Warp layout: 8 warps = 2(M) x 4(N); warp tile 64x40 = 4 m-tiles x 5 n-tiles.
// ---------------------------------------------------------------------------
__global__ __launch_bounds__(256, 2)
void mma_kernel(const float* __restrict__ G,
                const int*   __restrict__ m_ids,
                const int*   __restrict__ a_ids,
                const int*   __restrict__ spk_lbl,
                const float* __restrict__ mscores,
                const float* __restrict__ W2,
                const float* __restrict__ b2,
                int pair_mode) {
    __shared__ float As[TM * APAD];        // 18432 B
    __shared__ float Bs[TK * BPAD];        // 21504 B
    __shared__ float srow[4][TM];          //  2048 B
    __shared__ float bias_s[3 * TN];
    __shared__ float w2s[TN];

    const int tid = threadIdx.x;
    const int wid = tid >> 5, lane = tid & 31;
    const int gID = lane >> 2, tig = lane & 3;
    const int warp_m = wid & 1, warp_n = wid >> 1;
    const int base = blockIdx.x * TM;

    if (tid < TN) w2s[tid] = (tid < HIDDEN) ? W2[tid] : 0.f;
    for (int i = tid; i < 3 * TN; i += 256) bias_s[i] = d_bias[i];

    const float* Wp = d_Wp + (size_t)(pair_mode ? 2 : blockIdx.y) * G_DIM * TN;

    // staging roles: 2 threads per A row, each covers 16 k
    const int row = tid >> 1, half = tid & 1;
    const float *rowI, *rowJ = nullptr;
    if (pair_mode) {
        int ii = m_ids[base + row], jj = a_ids[base + row];
        rowI = G + (size_t)ii * G_DIM + half * 16;
        rowJ = G + (size_t)jj * G_DIM + half * 16;
    } else {
        rowI = G + (size_t)(base + row) * G_DIM + half * 16;
    }
    float* Arow = As + row * APAD + half * 16;

    float acc[4][5][4];
    #pragma unroll
    for (int a = 0; a < 4; a++)
        #pragma unroll
        for (int b = 0; b < 5; b++)
            #pragma unroll
            for (int c = 0; c < 4; c++) acc[a][b][c] = 0.f;

    for (int ch = 0; ch < NCHUNK; ch++) {
        const int k0 = ch * TK;
        // ---- stage A (pair products or raw rows, tf32-rounded) ----
        #pragma unroll
        for (int q = 0; q < 4; q++) {
            float4 vi = *reinterpret_cast<const float4*>(rowI + k0 + q * 4);
            float4 w;
            if (pair_mode) {
                float4 vj = *reinterpret_cast<const float4*>(rowJ + k0 + q * 4);
                w.x = __uint_as_float(f2tf32(vi.x * vj.x));
                w.y = __uint_as_float(f2tf32(vi.y * vj.y));
                w.z = __uint_as_float(f2tf32(vi.z * vj.z));
                w.w = __uint_as_float(f2tf32(vi.w * vj.w));
            } else {
                w.x = __uint_as_float(f2tf32(vi.x));
                w.y = __uint_as_float(f2tf32(vi.y));
                w.z = __uint_as_float(f2tf32(vi.z));
                w.w = __uint_as_float(f2tf32(vi.w));
            }
            *reinterpret_cast<float4*>(Arow + q * 4) = w;
        }
        // ---- stage B: straight copy of pre-rounded Wp rows ----
        #pragma unroll
        for (int it = 0; it < 5; it++) {
            int u = tid + it * 256;          // 0..1279 float4 units
            int k = u / 40, hq = u - k * 40;
            float4 w = *reinterpret_cast<const float4*>(
                Wp + (size_t)(k0 + k) * TN + hq * 4);
            *reinterpret_cast<float4*>(Bs + k * BPAD + hq * 4) = w;
        }
        __syncthreads();

        const uint32_t* Au = reinterpret_cast<const uint32_t*>(As);
        const uint32_t* Bu = reinterpret_cast<const uint32_t*>(Bs);
        #pragma unroll
        for (int ks = 0; ks < 4; ks++) {
            uint32_t af[4][4];
            #pragma unroll
            for (int tm = 0; tm < 4; tm++) {
                int b0 = (warp_m * 64 + tm * 16 + gID) * APAD + ks * 8 + tig;
                af[tm][0] = Au[b0];
                af[tm][1] = Au[b0 + 8 * APAD];
                af[tm][2] = Au[b0 + 4];
                af[tm][3] = Au[b0 + 8 * APAD + 4];
            }
            uint32_t bf[5][2];
            #pragma unroll
            for (int tn = 0; tn < 5; tn++) {
                int col = warp_n * 40 + tn * 8 + gID;
                bf[tn][0] = Bu[(ks * 8 + tig) * BPAD + col];
                bf[tn][1] = Bu[(ks * 8 + 4 + tig) * BPAD + col];
            }
            #pragma unroll
            for (int tm = 0; tm < 4; tm++)
                #pragma unroll
                for (int tn = 0; tn < 5; tn++)
                    mma_tf32(acc[tm][tn], af[tm], bf[tn]);
        }
        __syncthreads();
    }

    // ---- epilogue ----
    if (pair_mode) {
        for (int i = tid; i < 4 * TM; i += 256)
            (&srow[0][0])[i] = 0.f;
        __syncthreads();
        #pragma unroll
        for (int tm = 0; tm < 4; tm++) {
            #pragma unroll
            for (int rh = 0; rh < 2; rh++) {
                const int lr = warp_m * 64 + tm * 16 + rh * 8 + gID;
                const int p = base + lr;
                const int ii = m_ids[p], jj = a_ids[p], sp = spk_lbl[p];
                const float* Ar = d_Abuf + (size_t)ii * TN;
                const float* Br = d_Bbuf + (size_t)jj * TN;
                const float* bi = bias_s + sp * TN;
                float part = 0.f;
                #pragma unroll
                for (int tn = 0; tn < 5; tn++) {
                    #pragma unroll
                    for (int c2 = 0; c2 < 2; c2++) {
                        const int h = warp_n * 40 + tn * 8 + tig * 2 + c2;
                        float v = acc[tm][tn][rh * 2 + c2] + Ar[h] + Br[h] + bi[h];
                        part = fmaf(fmaxf(v, 0.f), w2s[h], part);
                    }
                }
                part += __shfl_xor_sync(0xffffffffu, part, 1);
                part += __shfl_xor_sync(0xffffffffu, part, 2);
                if (tig == 0) srow[warp_n][lr] = part;
            }
        }
        __syncthreads();
        if (tid < TM) {
            const int p = base + tid;
            d_scores[p] = srow[0][tid] + srow[1][tid] + srow[2][tid] + srow[3][tid]
                        + b2[0] + mscores[m_ids[p]] + mscores[a_ids[p]];
        }
    } else {
        float* out = (blockIdx.y == 0) ? d_Abuf : d_Bbuf;
        #pragma unroll
        for (int tm = 0; tm < 4; tm++) {
            #pragma unroll
            for (int rh = 0; rh < 2; rh++) {
                const int m = base + warp_m * 64 + tm * 16 + rh * 8 + gID;
                #pragma unroll
                for (int tn = 0; tn < 5; tn++) {
                    #pragma unroll
                    for (int c2 = 0; c2 < 2; c2++) {
                        const int h = warp_n * 40 + tn * 8 + tig * 2 + c2;
                        out[(size_t)m * TN + h] = acc[tm][tn][rh * 2 + c2];
                    }
                }
            }
        }
    }
}

// ---------------------------------------------------------------------------
// Ragged softmax with epsilon logit 0. One block per segment (sorted ids).
// ---------------------------------------------------------------------------
__global__ void softmax_kernel(const int* __restrict__ seg_ids,
                               float* __restrict__ out) {
    const int s = blockIdx.x;
    __shared__ int sh_lo, sh_hi;
    __shared__ float red[128];

    if (threadIdx.x == 0) {
        int lo = 0, hi = N_PAIRS;
        while (lo < hi) { int mid = (lo + hi) >> 1; if (seg_ids[mid] < s) lo = mid + 1; else hi = mid; }
        sh_lo = lo;
        hi = N_PAIRS;
        while (lo < hi) { int mid = (lo + hi) >> 1; if (seg_ids[mid] < s + 1) lo = mid + 1; else hi = mid; }
        sh_hi = lo;
    }
    __syncthreads();
    const int lo = sh_lo, hi = sh_hi;

    float m = 0.f;
    for (int p = lo + threadIdx.x; p < hi; p += blockDim.x)
        m = fmaxf(m, d_scores[p]);
    red[threadIdx.x] = m;
    __syncthreads();
    for (int st = 64; st; st >>= 1) {
        if (threadIdx.x < st) red[threadIdx.x] = fmaxf(red[threadIdx.x], red[threadIdx.x + st]);
        __syncthreads();
    }
    m = red[0];
    __syncthreads();

    float sum = 0.f;
    for (int p = lo + threadIdx.x; p < hi; p += blockDim.x)
        sum += expf(d_scores[p] - m);
    red[threadIdx.x] = sum;
    __syncthreads();
    for (int st = 64; st; st >>= 1) {
        if (threadIdx.x < st) red[threadIdx.x] += red[threadIdx.x + st];
        __syncthreads();
    }
    const float eps_e = expf(-m);
    const float inv_denom = 1.f / (red[0] + eps_e);

    for (int p = lo + threadIdx.x; p < hi; p += blockDim.x)
        out[p] = expf(d_scores[p] - m) * inv_denom;
    if (threadIdx.x == 0)
        out[N_PAIRS + s] = eps_e * inv_denom;
}

// ---------------------------------------------------------------------------
extern "C" void kernel_launch(void* const* d_in, const int* in_sizes, int n_in,
                              void* d_out, int out_size) {
    const float* g_i            = (const float*)d_in[0];
    const float* mention_scores = (const float*)d_in[1];
    const float* speaker_embed  = (const float*)d_in[2];
    const float* W1             = (const float*)d_in[3];
    const float* b1             = (const float*)d_in[4];
    const float* W2             = (const float*)d_in[5];
    const float* b2             = (const float*)d_in[6];
    const int*   mention_ids    = (const int*)d_in[7];
    const int*   antecedent_ids = (const int*)d_in[8];
    const int*   speaker_labels = (const int*)d_in[9];
    const int*   segment_ids    = (const int*)d_in[10];
    float* out = (float*)d_out;

    prep_w_kernel<<<(3 * G_DIM * TN + 255) / 256, 256>>>(W1);
    bias_kernel<<<1, 256>>>(speaker_embed, W1, b1);
    // precompute A/B: 32 M-tiles x 2 sections
    mma_kernel<<<dim3(N_MENT / TM, 2), 256>>>(g_i, mention_ids, antecedent_ids,
                                              speaker_labels, mention_scores,
                                              W2, b2, 0);
    // pair bilinear + fused epilogue
    mma_kernel<<<dim3(N_PAIRS / TM, 1), 256>>>(g_i, mention_ids, antecedent_ids,
                                               speaker_labels, mention_scores,
                                               W2, b2, 1);
    softmax_kernel<<<N_SEG, 128>>>(segment_ids, out);
}